// round 15
// baseline (speedup 1.0000x reference)
#include <cuda_runtime.h>
#include <cstdint>

#define NB   16384
#define NPG  9
#define RK   512
#define EPG  12
#define NN   (NB*NPG)
#define VOC  6

// ---------------- scratch (static device globals) ----------------------------
__device__ float g_m[(size_t)NN*RK];      // compact m1 rows (tf32, k-permuted)
__device__ float g_h[(size_t)NN*RK];      // compact h2 rows (GEMM1 out)
__device__ float g_mc[(size_t)NB*RK];     // layer-3 GEMM input (tf32, k-perm)
__device__ float g_Wt[3*RK*RK];           // tf32 W transposed [N][K], k-permuted
__device__ float g_EW0[VOC*RK];           // emb @ W0 (exact fp32)
__device__ uint4 g_metaA[NB];             // edges packed (3 ints) + feats (1)
__device__ uint4 g_metaB[NB];             // odeg, ideg, misc, s2list
__device__ unsigned g_gid[NN];            // per compact row: (graph<<4)|node
__device__ int   g_cnt[NB];
__device__ int   g_off[NB];
__device__ int   g_total;

__device__ __forceinline__ int kperm(int k){
    return (k & ~7) | ((k & 3) << 1) | ((k & 7) >> 2);
}
__device__ __forceinline__ float tf32r(float x){
    unsigned u; asm("cvt.rna.tf32.f32 %0, %1;" : "=r"(u) : "f"(x));
    return __uint_as_float(u);
}
__device__ __forceinline__ float wredsum(float v){
    #pragma unroll
    for (int o = 16; o; o >>= 1) v += __shfl_xor_sync(0xffffffffu, v, o);
    return v;
}
__device__ __forceinline__ void cp_async16(void* smem, const void* g){
    unsigned s = (unsigned)__cvta_generic_to_shared(smem);
    asm volatile("cp.async.cg.shared.global [%0], [%1], 16;\n" :: "r"(s), "l"(g));
}
__device__ __forceinline__ void cp_commit(){ asm volatile("cp.async.commit_group;\n"); }
template<int W> __device__ __forceinline__ void cp_wait(){
    asm volatile("cp.async.wait_group %0;\n" :: "n"(W));
}
__device__ __forceinline__ void mma_tf32(float* c, const unsigned* a, const unsigned* b){
    asm volatile(
        "mma.sync.aligned.m16n8k8.row.col.f32.tf32.tf32.f32 "
        "{%0,%1,%2,%3},{%4,%5,%6,%7},{%8,%9},{%0,%1,%2,%3};\n"
        : "+f"(c[0]), "+f"(c[1]), "+f"(c[2]), "+f"(c[3])
        : "r"(a[0]), "r"(a[1]), "r"(a[2]), "r"(a[3]), "r"(b[0]), "r"(b[1]));
}
__device__ __forceinline__ int read_idx(const void* p, int is64, long long i){
    return is64 ? (int)((const long long*)p)[i] : ((const int*)p)[i];
}

// meta accessors
#define EDGE_SD(A, e) (int)(((e) < 4 ? ((A).x >> ((e)*8)) : (e) < 8 ? ((A).y >> (((e)-4)*8)) : ((A).z >> (((e)-8)*8))) & 0xffu)
__device__ __forceinline__ float deg_nrm(unsigned lo8, unsigned hi, int n){
    int d = (int)((n < 8 ? (lo8 >> (4*n)) : hi) & 15u);
    return d ? rsqrtf((float)d) : 1.0f;
}
#define ONRM(B, n) deg_nrm((B).x, (B).z, n)
#define INRM(B, n) deg_nrm((B).y, (B).z >> 4, n)
#define S2CNT(B)   (int)(((B).z >> 8) & 15u)
#define NEEDM(B)   (((B).z >> 12) & 0x1FFu)
#define S2GET(B, j) (int)(((j) < 8 ? ((B).w >> (4*(j))) : ((B).z >> 21)) & 15u)
#define FEAT(A, n) (int)(((A).w >> (3*(n))) & 7u)

// === prep: W round/transpose + EW0 + META (with local dtype detect), 1 kernel
__global__ __launch_bounds__(256) void prep_kernel(
    const float* __restrict__ Ws, const float* __restrict__ emb,
    const void* __restrict__ featp, const void* __restrict__ srcp,
    const void* __restrict__ dstp)
{
    const int bx = blockIdx.x;
    if (bx < 512){
        __shared__ float t[32][33];
        const int L = 1 + (bx >> 8);
        const int k0 = (bx & 15)*32, n0 = ((bx >> 4) & 15)*32;
        const int tx = threadIdx.x & 31, ty = threadIdx.x >> 5;
        const float* src = Ws + (size_t)L*RK*RK;
        for (int i = ty; i < 32; i += 8)
            t[i][tx] = src[(size_t)(k0+i)*RK + n0 + tx];
        __syncthreads();
        float* dst = g_Wt + (size_t)L*RK*RK;
        for (int i = ty; i < 32; i += 8)
            dst[(size_t)(n0+i)*RK + k0 + kperm(tx)] = tf32r(t[tx][i]);
    } else if (bx < 524){
        const int v = (bx - 512) >> 1;
        const int f = ((bx - 512) & 1)*256 + threadIdx.x;
        float acc = 0.f;
        for (int k = 0; k < RK; k++)
            acc = fmaf(emb[(size_t)v*RK + k], Ws[(size_t)k*RK + f], acc);
        g_EW0[(size_t)v*RK + f] = acc;
    } else {
        // ---- meta section: local dtype detect, then pack one graph/thread ---
        __shared__ int s64s, f64s;
        if (threadIdx.x < 32){
            const int t = threadIdx.x;
            unsigned s = __ballot_sync(0xffffffffu, ((const int*)srcp)[2*t+1] != 0);
            unsigned f = __ballot_sync(0xffffffffu, ((const int*)featp)[2*t+1] != 0);
            if (t == 0){ s64s = (s == 0); f64s = (f == 0); }
        }
        __syncthreads();
        const int s64 = s64s, f64 = f64s;
        const int g = (bx - 524)*256 + threadIdx.x;

        int sl[EPG], dl[EPG];
        unsigned m0 = 0, m1 = 0, m2 = 0;
        #pragma unroll
        for (int e = 0; e < EPG; e++){
            long long idx = (long long)g*EPG + e;
            int s = read_idx(srcp, s64, idx) - g*NPG;
            int d = read_idx(dstp, s64, idx) - g*NPG;
            sl[e] = s; dl[e] = d;
            unsigned b = (unsigned)(s | (d << 4));
            if (e < 4)      m0 |= b << (e*8);
            else if (e < 8) m1 |= b << ((e-4)*8);
            else            m2 |= b << ((e-8)*8);
        }
        int od[NPG], id[NPG];
        #pragma unroll
        for (int n = 0; n < NPG; n++){ od[n] = 0; id[n] = 0; }
        #pragma unroll
        for (int e = 0; e < EPG; e++){ od[sl[e]]++; id[dl[e]]++; }
        unsigned mf = 0;
        #pragma unroll
        for (int n = 0; n < NPG; n++)
            mf |= (unsigned)read_idx(featp, f64, (long long)g*NPG + n) << (3*n);
        unsigned m4 = 0, m5 = 0;
        #pragma unroll
        for (int n = 0; n < 8; n++){ m4 |= (unsigned)od[n] << (4*n); m5 |= (unsigned)id[n] << (4*n); }

        unsigned seen = 0; int cnt = 0; int s2l[NPG];
        #pragma unroll
        for (int e = 0; e < EPG; e++){
            if (dl[e] == 0){
                int s = sl[e];
                if (!((seen >> s) & 1u)){ seen |= 1u << s; s2l[cnt++] = s; }
            }
        }
        unsigned need = 0;
        #pragma unroll
        for (int e = 0; e < EPG; e++)
            if ((seen >> dl[e]) & 1u) need |= 1u << sl[e];
        unsigned m7 = 0;
        for (int j = 0; j < cnt && j < 8; j++) m7 |= (unsigned)s2l[j] << (4*j);
        unsigned m6 = (unsigned)od[8] | ((unsigned)id[8] << 4) | ((unsigned)cnt << 8)
                    | (need << 12) | ((unsigned)((cnt > 8) ? s2l[8] : 0) << 21);

        g_metaA[g] = make_uint4(m0, m1, m2, mf);
        g_metaB[g] = make_uint4(m4, m5, m6, m7);
        g_cnt[g] = cnt;
    }
}

// --------- exclusive scan of g_cnt + emit row->graph/node map ----------------
__global__ __launch_bounds__(1024) void scan_kernel(){
    __shared__ int wsums[32];
    const int t = threadIdx.x, lane = t & 31, w = t >> 5;
    int c[16]; int s = 0;
    #pragma unroll
    for (int i = 0; i < 16; i++){ c[i] = g_cnt[t*16 + i]; s += c[i]; }
    int incl = s;
    #pragma unroll
    for (int o = 1; o < 32; o <<= 1){
        int v = __shfl_up_sync(0xffffffffu, incl, o);
        if (lane >= o) incl += v;
    }
    if (lane == 31) wsums[w] = incl;
    __syncthreads();
    if (w == 0){
        int iw = wsums[lane];
        #pragma unroll
        for (int o = 1; o < 32; o <<= 1){
            int u = __shfl_up_sync(0xffffffffu, iw, o);
            if (lane >= o) iw += u;
        }
        wsums[lane] = iw;
    }
    __syncthreads();
    int run = ((w == 0) ? 0 : wsums[w-1]) + incl - s;
    #pragma unroll
    for (int i = 0; i < 16; i++){
        const int g = t*16 + i;
        g_off[g] = run;
        if (c[i]){
            const uint4 B = g_metaB[g];
            for (int j = 0; j < c[i]; j++)
                g_gid[run + j] = ((unsigned)g << 4) | (unsigned)S2GET(B, j);
        }
        run += c[i];
    }
    if (t == 1023) g_total = run;
}

// ==== fuse1: 4 graphs/CTA, 2 warps/graph — h1/LN warp-per-row, 1 barrier =====
#define F1_G 4
#define F1_SMEM (F1_G*NPG*RK*4)

__global__ __launch_bounds__(256) void fuse1_kernel(
    const float* __restrict__ b0, const float* __restrict__ gam0,
    const float* __restrict__ bet0)
{
    extern __shared__ float hsbuf[];
    const int lane = threadIdx.x & 31, warp = threadIdx.x >> 5;
    const int q = warp >> 1, wq = warp & 1;      // graph slot, warp-in-pair
    const int g = blockIdx.x*F1_G + q;
    float (*hs)[RK] = (float(*)[RK])(hsbuf + (size_t)q*NPG*RK);
    const uint4 A = g_metaA[g];
    const uint4 B = g_metaB[g];
    const int cnt = S2CNT(B);
    const unsigned need = NEEDM(B);
    const int nneed = __popc(need);

    // stage B: warp pair covers needed rows (h1 + LN + relu + onrm scale)
    for (int t = wq; t < nneed; t += 2){
        int r = -1; unsigned m = need;
        for (int i = 0; i <= t; i++){ r = __ffs(m) - 1; m &= m - 1; }
        const float irow = INRM(B, r);
        const float orow = ONRM(B, r);
        float cf[VOC];
        #pragma unroll
        for (int v = 0; v < VOC; v++) cf[v] = 0.f;
        #pragma unroll
        for (int e = 0; e < EPG; e++){
            int sd = EDGE_SD(A, e);
            int s = sd & 15, d = sd >> 4;
            if (d == r){
                float w2 = ONRM(B, s);
                int fv = FEAT(A, s);
                #pragma unroll
                for (int v = 0; v < VOC; v++) cf[v] += (fv == v) ? w2 : 0.f;
            }
        }
        #pragma unroll
        for (int v = 0; v < VOC; v++) cf[v] *= irow;
        float h[16];
        #pragma unroll
        for (int u = 0; u < 16; u++) h[u] = b0[lane + 32*u];
        #pragma unroll
        for (int v = 0; v < VOC; v++){
            if (cf[v] != 0.f){               // warp-uniform
                const float* ew = g_EW0 + (size_t)v*RK;
                #pragma unroll
                for (int u = 0; u < 16; u++)
                    h[u] = fmaf(cf[v], ew[lane + 32*u], h[u]);
            }
        }
        float s = 0.f, ss = 0.f;
        #pragma unroll
        for (int u = 0; u < 16; u++){ s += h[u]; ss += h[u]*h[u]; }
        s = wredsum(s); ss = wredsum(ss);
        float mu = s*(1.0f/RK);
        float rs = rsqrtf(ss*(1.0f/RK) - mu*mu + 1e-5f);
        #pragma unroll
        for (int u = 0; u < 16; u++){
            float y = fmaxf((h[u]-mu)*rs*gam0[lane+32*u] + bet0[lane+32*u], 0.f);
            hs[r][lane + 32*u] = y*orow;
        }
    }
    __syncthreads();

    // stage C: warp pair builds m1 rows (edge-order sum), permuted tf32 store
    const int off = g_off[g];
    const int pl = kperm(lane);
    for (int j = wq; j < cnt; j += 2){
        const int target = S2GET(B, j);
        const float itg = INRM(B, target);
        float acc[16];
        #pragma unroll
        for (int u = 0; u < 16; u++) acc[u] = 0.f;
        #pragma unroll
        for (int e = 0; e < EPG; e++){
            int sd = EDGE_SD(A, e);
            int s = sd & 15, d = sd >> 4;
            if (d == target){                // warp-uniform
                #pragma unroll
                for (int u = 0; u < 16; u++) acc[u] += hs[s][lane + 32*u];
            }
        }
        float* dst = g_m + (size_t)(off + j)*RK;
        #pragma unroll
        for (int u = 0; u < 16; u++)
            dst[32*u + pl] = tf32r(acc[u]*itg);
    }
}

// ==== fuseD: 4 graphs/CTA, 2 warps/graph — LN per compact row, 1 barrier =====
__global__ __launch_bounds__(256) void fuseD_kernel(
    const float* __restrict__ b1, const float* __restrict__ gam1,
    const float* __restrict__ bet1)
{
    extern __shared__ float hsbuf[];
    const int lane = threadIdx.x & 31, warp = threadIdx.x >> 5;
    const int q = warp >> 1, wq = warp & 1;      // graph slot, warp-in-pair
    const int g = blockIdx.x*F1_G + q;
    float (*hs)[RK] = (float(*)[RK])(hsbuf + (size_t)q*NPG*RK);
    const uint4 A = g_metaA[g];
    const uint4 B = g_metaB[g];
    const int cnt = g_cnt[g], off = g_off[g];

    // stage A: warp pair LN's compact rows; scale = mult * onrm[node]
    for (int j = wq; j < cnt; j += 2){
        const int node = (int)(g_gid[off + j] & 15u);
        int mult = 0;
        #pragma unroll
        for (int e = 0; e < EPG; e++){
            int sd = EDGE_SD(A, e);
            mult += ((sd >> 4) == 0 && (sd & 15) == node);
        }
        const float scale = (float)mult * ONRM(B, node);
        const float* row = g_h + (size_t)(off + j)*RK;
        float x[16]; float s = 0.f, ss = 0.f;
        #pragma unroll
        for (int u = 0; u < 16; u++){
            float v = row[lane + 32*u] + b1[lane + 32*u];
            x[u] = v; s += v; ss += v*v;
        }
        s = wredsum(s); ss = wredsum(ss);
        const float mu = s*(1.0f/RK);
        const float rs = rsqrtf(ss*(1.0f/RK) - mu*mu + 1e-5f);
        #pragma unroll
        for (int u = 0; u < 16; u++){
            float y = fmaxf((x[u]-mu)*rs*gam1[lane+32*u] + bet1[lane+32*u], 0.f);
            hs[j][lane + 32*u] = y*scale;
        }
    }
    __syncthreads();

    // stage B: 2 warps split the 512 elements; sum rows, permuted tf32 store
    const float in0 = INRM(B, 0);
    float* dst = g_mc + (size_t)g*RK;
    #pragma unroll
    for (int u = 0; u < 8; u++){
        const int kk = wq*256 + u*32 + lane;
        float val = 0.f;
        for (int j = 0; j < cnt; j++) val += hs[j][kk];
        dst[kperm(kk)] = tf32r(val*in0);
    }
}

// ------------- GEMM1 (mma.sync tf32): g_h = g_m @ W1t, early exit ------------
#define BM 128
#define BN 256
#define BK 32
#define APITCH 40
#define BPITCH 40
#define STAGES 3
#define STG_F (BM*APITCH + BN*BPITCH)
#define SMEM_GEMM (STAGES*STG_F*4)

__global__ __launch_bounds__(256,1) void gemm_tf32_kernel(
    const float* __restrict__ A, const float* __restrict__ Wt,
    float* __restrict__ C, const int* __restrict__ tot)
{
    extern __shared__ float smbuf[];
    const int bn = blockIdx.x, bm = blockIdx.y;
    if (tot && bm*BM >= *tot) return;
    const int tid = threadIdx.x;
    const int lane = tid & 31, warp = tid >> 5;
    const int wm = warp & 1, wn = warp >> 1;
    const int gid = lane >> 2, tig = lane & 3;

    float c[4][8][4];
    #pragma unroll
    for (int mt = 0; mt < 4; mt++)
        #pragma unroll
        for (int nf = 0; nf < 8; nf++)
            #pragma unroll
            for (int q = 0; q < 4; q++) c[mt][nf][q] = 0.f;

    const float* Ag = A  + (size_t)bm*BM*RK;
    const float* Bg = Wt + (size_t)bn*BN*RK;

    auto fill = [&](int t){
        float* As = smbuf + (t % STAGES)*STG_F;
        float* Bs = As + BM*APITCH;
        const int k0 = t*BK;
        #pragma unroll
        for (int i = 0; i < 4; i++){
            int idx = tid + i*256; int r = idx >> 3, cc = idx & 7;
            cp_async16(&As[r*APITCH + cc*4], Ag + (size_t)r*RK + k0 + cc*4);
        }
        #pragma unroll
        for (int i = 0; i < 8; i++){
            int idx = tid + i*256; int r = idx >> 3, cc = idx & 7;
            cp_async16(&Bs[r*BPITCH + cc*4], Bg + (size_t)r*RK + k0 + cc*4);
        }
        cp_commit();
    };

    fill(0); fill(1);

    #pragma unroll 1
    for (int kt = 0; kt < RK/BK; kt++){
        cp_wait<1>();
        __syncthreads();
        if (kt + 2 < RK/BK) fill(kt + 2);
        else cp_commit();

        const float* Ac = smbuf + (kt % STAGES)*STG_F;
        const float* Bc = Ac + BM*APITCH;
        #pragma unroll
        for (int ks = 0; ks < BK/8; ks++){
            const int kp = ks*8 + 2*tig;
            unsigned a[4][4]; unsigned b[8][2];
            #pragma unroll
            for (int mt = 0; mt < 4; mt++){
                int r = wm*64 + mt*16 + gid;
                float2 p0 = *(const float2*)&Ac[ r    *APITCH + kp];
                float2 p1 = *(const float2*)&Ac[(r+8) *APITCH + kp];
                a[mt][0] = __float_as_uint(p0.x);
                a[mt][1] = __float_as_uint(p1.x);
                a[mt][2] = __float_as_uint(p0.y);
                a[mt][3] = __float_as_uint(p1.y);
            }
            #pragma unroll
            for (int nf = 0; nf < 8; nf++){
                int cn = wn*64 + nf*8 + gid;
                float2 pb = *(const float2*)&Bc[cn*BPITCH + kp];
                b[nf][0] = __float_as_uint(pb.x);
                b[nf][1] = __float_as_uint(pb.y);
            }
            #pragma unroll
            for (int mt = 0; mt < 4; mt++)
                #pragma unroll
                for (int nf = 0; nf < 8; nf++)
                    mma_tf32(c[mt][nf], a[mt], b[nf]);
        }
    }
    #pragma unroll
    for (int mt = 0; mt < 4; mt++){
        int r = bm*BM + wm*64 + mt*16 + gid;
        #pragma unroll
        for (int nf = 0; nf < 8; nf++){
            int cn = bn*BN + wn*64 + nf*8 + tig*2;
            *(float2*)&C[(size_t)r*RK + cn]     = make_float2(c[mt][nf][0], c[mt][nf][1]);
            *(float2*)&C[(size_t)(r+8)*RK + cn] = make_float2(c[mt][nf][2], c[mt][nf][3]);
        }
    }
}

// ----- GEMM2 fused with output head: out = relu(LN(mc@W2t + b2))·wout + bout -
#define BM2 64
#define STG2_F (BM2*APITCH + 512*BPITCH)
#define SMEM_G2 (2*STG2_F*4)

__global__ __launch_bounds__(256,1) void gemm2_out_kernel(
    const float* __restrict__ A, const float* __restrict__ Wt,
    const float* __restrict__ b2, const float* __restrict__ gm2,
    const float* __restrict__ bt2, const float* __restrict__ wout,
    const float* __restrict__ bout, float* __restrict__ out)
{
    extern __shared__ float smbuf[];
    const int tid = threadIdx.x, bm = blockIdx.x;
    const int lane = tid & 31, w = tid >> 5;
    const int gid = lane >> 2, tig = lane & 3;

    float c[4][8][4];
    #pragma unroll
    for (int mt = 0; mt < 4; mt++)
        #pragma unroll
        for (int nf = 0; nf < 8; nf++)
            #pragma unroll
            for (int q = 0; q < 4; q++) c[mt][nf][q] = 0.f;

    const float* Ag = A + (size_t)bm*BM2*RK;

    auto fill = [&](int t){
        float* As = smbuf + (t & 1)*STG2_F;
        float* Bs = As + BM2*APITCH;
        const int k0 = t*BK;
        #pragma unroll
        for (int i = 0; i < 2; i++){
            int idx = tid + i*256; int r = idx >> 3, cc = idx & 7;
            cp_async16(&As[r*APITCH + cc*4], Ag + (size_t)r*RK + k0 + cc*4);
        }
        #pragma unroll
        for (int i = 0; i < 16; i++){
            int idx = tid + i*256; int r = idx >> 3, cc = idx & 7;
            cp_async16(&Bs[r*BPITCH + cc*4], Wt + (size_t)r*RK + k0 + cc*4);
        }
        cp_commit();
    };

    fill(0);
    #pragma unroll 1
    for (int kt = 0; kt < RK/BK; kt++){
        if (kt + 1 < RK/BK){ fill(kt + 1); cp_wait<1>(); }
        else               { cp_wait<0>(); }
        __syncthreads();
        const float* Ac = smbuf + (kt & 1)*STG2_F;
        const float* Bc = Ac + BM2*APITCH;
        #pragma unroll
        for (int ks = 0; ks < BK/8; ks++){
            const int kp = ks*8 + 2*tig;
            unsigned a[4][4]; unsigned b[8][2];
            #pragma unroll
            for (int mt = 0; mt < 4; mt++){
                int r = mt*16 + gid;
                float2 p0 = *(const float2*)&Ac[ r    *APITCH + kp];
                float2 p1 = *(const float2*)&Ac[(r+8) *APITCH + kp];
                a[mt][0] = __float_as_uint(p0.x);
                a[mt][1] = __float_as_uint(p1.x);
                a[mt][2] = __float_as_uint(p0.y);
                a[mt][3] = __float_as_uint(p1.y);
            }
            #pragma unroll
            for (int nf = 0; nf < 8; nf++){
                int cn = w*64 + nf*8 + gid;
                float2 pb = *(const float2*)&Bc[cn*BPITCH + kp];
                b[nf][0] = __float_as_uint(pb.x);
                b[nf][1] = __float_as_uint(pb.y);
            }
            #pragma unroll
            for (int mt = 0; mt < 4; mt++)
                #pragma unroll
                for (int nf = 0; nf < 8; nf++)
                    mma_tf32(c[mt][nf], a[mt], b[nf]);
        }
        __syncthreads();
    }

    // fused epilogue: bias -> LN (cross-warp) -> ReLU -> dot(wout)
    float* sS  = smbuf;
    float* sQ  = smbuf + 512;
    float* sMu = smbuf + 1024;
    float* sRs = smbuf + 1088;
    float* sD  = smbuf + 2048;

    float b2v[8][2], g2v[8][2], t2v[8][2], wov[8][2];
    #pragma unroll
    for (int nf = 0; nf < 8; nf++){
        int col = w*64 + nf*8 + tig*2;
        b2v[nf][0] = b2[col];   b2v[nf][1] = b2[col+1];
        g2v[nf][0] = gm2[col];  g2v[nf][1] = gm2[col+1];
        t2v[nf][0] = bt2[col];  t2v[nf][1] = bt2[col+1];
        wov[nf][0] = wout[col]; wov[nf][1] = wout[col+1];
    }
    float ps[4][2], pq[4][2];
    #pragma unroll
    for (int mt = 0; mt < 4; mt++)
        #pragma unroll
        for (int h = 0; h < 2; h++){ ps[mt][h] = 0.f; pq[mt][h] = 0.f; }
    #pragma unroll
    for (int mt = 0; mt < 4; mt++)
        #pragma unroll
        for (int nf = 0; nf < 8; nf++)
            #pragma unroll
            for (int q = 0; q < 4; q++){
                float v = c[mt][nf][q] + b2v[nf][q & 1];
                c[mt][nf][q] = v;
                ps[mt][q >> 1] += v;
                pq[mt][q >> 1] += v*v;
            }
    #pragma unroll
    for (int mt = 0; mt < 4; mt++)
        #pragma unroll
        for (int h = 0; h < 2; h++){
            float s = ps[mt][h], q = pq[mt][h];
            s += __shfl_xor_sync(0xffffffffu, s, 1);
            s += __shfl_xor_sync(0xffffffffu, s, 2);
            q += __shfl_xor_sync(0xffffffffu, q, 1);
            q += __shfl_xor_sync(0xffffffffu, q, 2);
            if (tig == 0){
                int r = mt*16 + 8*h + gid;
                sS[w*64 + r] = s;
                sQ[w*64 + r] = q;
            }
        }
    __syncthreads();
    if (tid < 64){
        float S = 0.f, Q = 0.f;
        #pragma unroll
        for (int ww = 0; ww < 8; ww++){ S += sS[ww*64 + tid]; Q += sQ[ww*64 + tid]; }
        float mu = S*(1.0f/RK);
        sMu[tid] = mu;
        sRs[tid] = rsqrtf(Q*(1.0f/RK) - mu*mu + 1e-5f);
    }
    __syncthreads();
    float pd[4][2];
    #pragma unroll
    for (int mt = 0; mt < 4; mt++)
        #pragma unroll
        for (int h = 0; h < 2; h++){
            int r = mt*16 + 8*h + gid;
            float mu = sMu[r], rs = sRs[r];
            float acc = 0.f;
            #pragma unroll
            for (int nf = 0; nf < 8; nf++)
                #pragma unroll
                for (int qq = 0; qq < 2; qq++){
                    float y = fmaxf((c[mt][nf][2*h+qq] - mu)*rs*g2v[nf][qq] + t2v[nf][qq], 0.f);
                    acc = fmaf(y, wov[nf][qq], acc);
                }
            pd[mt][h] = acc;
        }
    #pragma unroll
    for (int mt = 0; mt < 4; mt++)
        #pragma unroll
        for (int h = 0; h < 2; h++){
            float s = pd[mt][h];
            s += __shfl_xor_sync(0xffffffffu, s, 1);
            s += __shfl_xor_sync(0xffffffffu, s, 2);
            if (tig == 0) sD[w*64 + mt*16 + 8*h + gid] = s;
        }
    __syncthreads();
    if (tid < 64){
        float dot = 0.f;
        #pragma unroll
        for (int ww = 0; ww < 8; ww++) dot += sD[ww*64 + tid];
        out[bm*BM2 + tid] = dot + bout[0];
    }
}

// ---------------- launcher ---------------------------------------------------
extern "C" void kernel_launch(void* const* d_in, const int* in_sizes, int n_in,
                              void* d_out, int out_size){
    (void)in_sizes; (void)n_in; (void)out_size;
    const void*  feat = d_in[0];
    const void*  src  = d_in[1];
    const void*  dst  = d_in[2];
    const float* emb  = (const float*)d_in[3];
    const float* Ws   = (const float*)d_in[4];
    const float* bs   = (const float*)d_in[5];
    const float* gam  = (const float*)d_in[6];
    const float* bet  = (const float*)d_in[7];
    const float* wout = (const float*)d_in[8];
    const float* bout = (const float*)d_in[9];
    float* out = (float*)d_out;

    cudaFuncSetAttribute(gemm_tf32_kernel,
                         cudaFuncAttributeMaxDynamicSharedMemorySize, SMEM_GEMM);
    cudaFuncSetAttribute(gemm2_out_kernel,
                         cudaFuncAttributeMaxDynamicSharedMemorySize, SMEM_G2);
    cudaFuncSetAttribute(fuse1_kernel,
                         cudaFuncAttributeMaxDynamicSharedMemorySize, F1_SMEM);
    cudaFuncSetAttribute(fuseD_kernel,
                         cudaFuncAttributeMaxDynamicSharedMemorySize, F1_SMEM);

    float* gm;  cudaGetSymbolAddress((void**)&gm,  g_m);
    float* gh;  cudaGetSymbolAddress((void**)&gh,  g_h);
    float* gmc; cudaGetSymbolAddress((void**)&gmc, g_mc);
    float* gwt; cudaGetSymbolAddress((void**)&gwt, g_Wt);
    int*   gtot; cudaGetSymbolAddress((void**)&gtot, g_total);

    prep_kernel<<<524 + NB/256, 256>>>(Ws, emb, feat, src, dst);
    scan_kernel<<<1, 1024>>>();

    fuse1_kernel<<<NB/F1_G, 256, F1_SMEM>>>(bs, gam, bet);
    dim3 gg(RK/BN, NN/BM);                 // worst case; early exit on g_total
    gemm_tf32_kernel<<<gg, 256, SMEM_GEMM>>>(gm, gwt + RK*RK, gh, gtot);
    fuseD_kernel<<<NB/F1_G, 256, F1_SMEM>>>(bs + RK, gam + RK, bet + RK);
    gemm2_out_kernel<<<NB/BM2, 256, SMEM_G2>>>(gmc, gwt + 2*(size_t)RK*RK,
        bs + 2*RK, gam + 2*RK, bet + 2*RK, wout, bout, out);
}

// round 16
// speedup vs baseline: 1.4026x; 1.4026x over previous
#include <cuda_runtime.h>
#include <cstdint>

#define NB   16384
#define NPG  9
#define RK   512
#define EPG  12
#define NN   (NB*NPG)
#define VOC  6

// ---------------- scratch (static device globals) ----------------------------
__device__ float g_m[(size_t)NN*RK];      // compact m1 rows (tf32, k-permuted)
__device__ float g_h[(size_t)NN*RK];      // compact h2 rows (GEMM1 out)
__device__ float g_mc[(size_t)NB*RK];     // layer-3 GEMM input (tf32, k-perm)
__device__ float g_Wt[3*RK*RK];           // tf32 W transposed [N][K], k-permuted
__device__ float g_EW0[VOC*RK];           // emb @ W0 (exact fp32)
__device__ uint4 g_metaA[NB];             // edges packed (3 ints) + feats (1)
__device__ uint4 g_metaB[NB];             // odeg, ideg, misc, s2list
__device__ unsigned g_gid[NN];            // per compact row: (graph<<4)|node
__device__ int   g_cnt[NB];
__device__ int   g_off[NB];
__device__ int   g_total;
__device__ int   g_src64;
__device__ int   g_feat64;

__device__ __forceinline__ int kperm(int k){
    return (k & ~7) | ((k & 3) << 1) | ((k & 7) >> 2);
}
__device__ __forceinline__ float tf32r(float x){
    unsigned u; asm("cvt.rna.tf32.f32 %0, %1;" : "=r"(u) : "f"(x));
    return __uint_as_float(u);
}
__device__ __forceinline__ float wredsum(float v){
    #pragma unroll
    for (int o = 16; o; o >>= 1) v += __shfl_xor_sync(0xffffffffu, v, o);
    return v;
}
__device__ __forceinline__ void cp_async16(void* smem, const void* g){
    unsigned s = (unsigned)__cvta_generic_to_shared(smem);
    asm volatile("cp.async.cg.shared.global [%0], [%1], 16;\n" :: "r"(s), "l"(g));
}
__device__ __forceinline__ void cp_commit(){ asm volatile("cp.async.commit_group;\n"); }
template<int W> __device__ __forceinline__ void cp_wait(){
    asm volatile("cp.async.wait_group %0;\n" :: "n"(W));
}
__device__ __forceinline__ void mma_tf32(float* c, const unsigned* a, const unsigned* b){
    asm volatile(
        "mma.sync.aligned.m16n8k8.row.col.f32.tf32.tf32.f32 "
        "{%0,%1,%2,%3},{%4,%5,%6,%7},{%8,%9},{%0,%1,%2,%3};\n"
        : "+f"(c[0]), "+f"(c[1]), "+f"(c[2]), "+f"(c[3])
        : "r"(a[0]), "r"(a[1]), "r"(a[2]), "r"(a[3]), "r"(b[0]), "r"(b[1]));
}
__device__ __forceinline__ int read_idx(const void* p, int is64, long long i){
    return is64 ? (int)((const long long*)p)[i] : ((const int*)p)[i];
}

// meta accessors
#define EDGE_SD(A, e) (int)(((e) < 4 ? ((A).x >> ((e)*8)) : (e) < 8 ? ((A).y >> (((e)-4)*8)) : ((A).z >> (((e)-8)*8))) & 0xffu)
__device__ __forceinline__ float deg_nrm(unsigned lo8, unsigned hi, int n){
    int d = (int)((n < 8 ? (lo8 >> (4*n)) : hi) & 15u);
    return d ? rsqrtf((float)d) : 1.0f;
}
#define ONRM(B, n) deg_nrm((B).x, (B).z, n)
#define INRM(B, n) deg_nrm((B).y, (B).z >> 4, n)
#define S2CNT(B)   (int)(((B).z >> 8) & 15u)
#define NEEDM(B)   (((B).z >> 12) & 0x1FFu)
#define S2GET(B, j) (int)(((j) < 8 ? ((B).w >> (4*(j))) : ((B).z >> 21)) & 15u)
#define FEAT(A, n) (int)(((A).w >> (3*(n))) & 7u)

// ======= prep: detect dtypes + round/transpose W(1,2) + EW0 in ONE kernel ====
__global__ __launch_bounds__(256) void prep_kernel(
    const float* __restrict__ Ws, const float* __restrict__ emb,
    const int* __restrict__ sw, const int* __restrict__ fw)
{
    const int bx = blockIdx.x;
    if (bx < 512){
        __shared__ float t[32][33];
        const int L = 1 + (bx >> 8);
        const int k0 = (bx & 15)*32, n0 = ((bx >> 4) & 15)*32;
        const int tx = threadIdx.x & 31, ty = threadIdx.x >> 5;
        const float* src = Ws + (size_t)L*RK*RK;
        for (int i = ty; i < 32; i += 8)
            t[i][tx] = src[(size_t)(k0+i)*RK + n0 + tx];
        __syncthreads();
        float* dst = g_Wt + (size_t)L*RK*RK;
        for (int i = ty; i < 32; i += 8)
            dst[(size_t)(n0+i)*RK + k0 + kperm(tx)] = tf32r(t[tx][i]);
    } else if (bx < 524){
        const int v = (bx - 512) >> 1;
        const int f = ((bx - 512) & 1)*256 + threadIdx.x;
        float acc = 0.f;
        for (int k = 0; k < RK; k++)
            acc = fmaf(emb[(size_t)v*RK + k], Ws[(size_t)k*RK + f], acc);
        g_EW0[(size_t)v*RK + f] = acc;
    } else {
        if (threadIdx.x < 32){
            const int t = threadIdx.x;
            unsigned s = __ballot_sync(0xffffffffu, sw[2*t+1] != 0);
            unsigned f = __ballot_sync(0xffffffffu, fw[2*t+1] != 0);
            if (t == 0){ g_src64 = (s == 0); g_feat64 = (f == 0); }
        }
    }
}

// ======= meta: pack topology per graph (one thread per graph) ================
__global__ void meta_kernel(const void* __restrict__ featp,
                            const void* __restrict__ srcp,
                            const void* __restrict__ dstp){
    const int g = blockIdx.x*256 + threadIdx.x;
    const int s64 = g_src64, f64 = g_feat64;
    int sl[EPG], dl[EPG];
    unsigned m0 = 0, m1 = 0, m2 = 0;
    #pragma unroll
    for (int e = 0; e < EPG; e++){
        long long idx = (long long)g*EPG + e;
        int s = read_idx(srcp, s64, idx) - g*NPG;
        int d = read_idx(dstp, s64, idx) - g*NPG;
        sl[e] = s; dl[e] = d;
        unsigned b = (unsigned)(s | (d << 4));
        if (e < 4)      m0 |= b << (e*8);
        else if (e < 8) m1 |= b << ((e-4)*8);
        else            m2 |= b << ((e-8)*8);
    }
    int od[NPG], id[NPG];
    #pragma unroll
    for (int n = 0; n < NPG; n++){ od[n] = 0; id[n] = 0; }
    #pragma unroll
    for (int e = 0; e < EPG; e++){ od[sl[e]]++; id[dl[e]]++; }
    unsigned mf = 0;
    #pragma unroll
    for (int n = 0; n < NPG; n++)
        mf |= (unsigned)read_idx(featp, f64, (long long)g*NPG + n) << (3*n);
    unsigned m4 = 0, m5 = 0;
    #pragma unroll
    for (int n = 0; n < 8; n++){ m4 |= (unsigned)od[n] << (4*n); m5 |= (unsigned)id[n] << (4*n); }

    unsigned seen = 0; int cnt = 0; int s2l[NPG];
    #pragma unroll
    for (int e = 0; e < EPG; e++){
        if (dl[e] == 0){
            int s = sl[e];
            if (!((seen >> s) & 1u)){ seen |= 1u << s; s2l[cnt++] = s; }
        }
    }
    unsigned need = 0;
    #pragma unroll
    for (int e = 0; e < EPG; e++)
        if ((seen >> dl[e]) & 1u) need |= 1u << sl[e];
    unsigned m7 = 0;
    for (int j = 0; j < cnt && j < 8; j++) m7 |= (unsigned)s2l[j] << (4*j);
    unsigned m6 = (unsigned)od[8] | ((unsigned)id[8] << 4) | ((unsigned)cnt << 8)
                | (need << 12) | ((unsigned)((cnt > 8) ? s2l[8] : 0) << 21);

    g_metaA[g] = make_uint4(m0, m1, m2, mf);
    g_metaB[g] = make_uint4(m4, m5, m6, m7);
    g_cnt[g] = cnt;
}

// --------- exclusive scan of g_cnt + emit row->graph/node map ----------------
__global__ __launch_bounds__(1024) void scan_kernel(){
    __shared__ int wsums[32];
    const int t = threadIdx.x, lane = t & 31, w = t >> 5;
    int c[16]; int s = 0;
    #pragma unroll
    for (int i = 0; i < 16; i++){ c[i] = g_cnt[t*16 + i]; s += c[i]; }
    int incl = s;
    #pragma unroll
    for (int o = 1; o < 32; o <<= 1){
        int v = __shfl_up_sync(0xffffffffu, incl, o);
        if (lane >= o) incl += v;
    }
    if (lane == 31) wsums[w] = incl;
    __syncthreads();
    if (w == 0){
        int iw = wsums[lane];
        #pragma unroll
        for (int o = 1; o < 32; o <<= 1){
            int u = __shfl_up_sync(0xffffffffu, iw, o);
            if (lane >= o) iw += u;
        }
        wsums[lane] = iw;
    }
    __syncthreads();
    int run = ((w == 0) ? 0 : wsums[w-1]) + incl - s;
    #pragma unroll
    for (int i = 0; i < 16; i++){
        const int g = t*16 + i;
        g_off[g] = run;
        if (c[i]){
            const uint4 B = g_metaB[g];
            for (int j = 0; j < c[i]; j++)
                g_gid[run + j] = ((unsigned)g << 4) | (unsigned)S2GET(B, j);
        }
        run += c[i];
    }
    if (t == 1023) g_total = run;
}

// ==== fuse1: 4 graphs/CTA, 2 warps/graph — h1/LN warp-per-row, 1 barrier =====
#define F1_G 4
#define F1_SMEM (F1_G*NPG*RK*4)

__global__ __launch_bounds__(256) void fuse1_kernel(
    const float* __restrict__ b0, const float* __restrict__ gam0,
    const float* __restrict__ bet0)
{
    extern __shared__ float hsbuf[];
    const int lane = threadIdx.x & 31, warp = threadIdx.x >> 5;
    const int q = warp >> 1, wq = warp & 1;      // graph slot, warp-in-pair
    const int g = blockIdx.x*F1_G + q;
    float (*hs)[RK] = (float(*)[RK])(hsbuf + (size_t)q*NPG*RK);
    const uint4 A = g_metaA[g];
    const uint4 B = g_metaB[g];
    const int cnt = S2CNT(B);
    const unsigned need = NEEDM(B);
    const int nneed = __popc(need);

    // stage B: warp pair covers needed rows (h1 + LN + relu + onrm scale)
    for (int t = wq; t < nneed; t += 2){
        int r = -1; unsigned m = need;
        for (int i = 0; i <= t; i++){ r = __ffs(m) - 1; m &= m - 1; }
        const float irow = INRM(B, r);
        const float orow = ONRM(B, r);
        float cf[VOC];
        #pragma unroll
        for (int v = 0; v < VOC; v++) cf[v] = 0.f;
        #pragma unroll
        for (int e = 0; e < EPG; e++){
            int sd = EDGE_SD(A, e);
            int s = sd & 15, d = sd >> 4;
            if (d == r){
                float w2 = ONRM(B, s);
                int fv = FEAT(A, s);
                #pragma unroll
                for (int v = 0; v < VOC; v++) cf[v] += (fv == v) ? w2 : 0.f;
            }
        }
        #pragma unroll
        for (int v = 0; v < VOC; v++) cf[v] *= irow;
        float h[16];
        #pragma unroll
        for (int u = 0; u < 16; u++) h[u] = b0[lane + 32*u];
        #pragma unroll
        for (int v = 0; v < VOC; v++){
            if (cf[v] != 0.f){               // warp-uniform
                const float* ew = g_EW0 + (size_t)v*RK;
                #pragma unroll
                for (int u = 0; u < 16; u++)
                    h[u] = fmaf(cf[v], ew[lane + 32*u], h[u]);
            }
        }
        float s = 0.f, ss = 0.f;
        #pragma unroll
        for (int u = 0; u < 16; u++){ s += h[u]; ss += h[u]*h[u]; }
        s = wredsum(s); ss = wredsum(ss);
        float mu = s*(1.0f/RK);
        float rs = rsqrtf(ss*(1.0f/RK) - mu*mu + 1e-5f);
        #pragma unroll
        for (int u = 0; u < 16; u++){
            float y = fmaxf((h[u]-mu)*rs*gam0[lane+32*u] + bet0[lane+32*u], 0.f);
            hs[r][lane + 32*u] = y*orow;
        }
    }
    __syncthreads();

    // stage C: warp pair builds m1 rows (edge-order sum), permuted tf32 store
    const int off = g_off[g];
    const int pl = kperm(lane);
    for (int j = wq; j < cnt; j += 2){
        const int target = S2GET(B, j);
        const float itg = INRM(B, target);
        float acc[16];
        #pragma unroll
        for (int u = 0; u < 16; u++) acc[u] = 0.f;
        #pragma unroll
        for (int e = 0; e < EPG; e++){
            int sd = EDGE_SD(A, e);
            int s = sd & 15, d = sd >> 4;
            if (d == target){                // warp-uniform
                #pragma unroll
                for (int u = 0; u < 16; u++) acc[u] += hs[s][lane + 32*u];
            }
        }
        float* dst = g_m + (size_t)(off + j)*RK;
        #pragma unroll
        for (int u = 0; u < 16; u++)
            dst[32*u + pl] = tf32r(acc[u]*itg);
    }
}

// ==== fuseD: 4 graphs/CTA, 2 warps/graph — LN per compact row, 1 barrier =====
__global__ __launch_bounds__(256) void fuseD_kernel(
    const float* __restrict__ b1, const float* __restrict__ gam1,
    const float* __restrict__ bet1)
{
    extern __shared__ float hsbuf[];
    const int lane = threadIdx.x & 31, warp = threadIdx.x >> 5;
    const int q = warp >> 1, wq = warp & 1;      // graph slot, warp-in-pair
    const int g = blockIdx.x*F1_G + q;
    float (*hs)[RK] = (float(*)[RK])(hsbuf + (size_t)q*NPG*RK);
    const uint4 A = g_metaA[g];
    const uint4 B = g_metaB[g];
    const int cnt = g_cnt[g], off = g_off[g];

    // stage A: warp pair LN's compact rows; scale = mult * onrm[node]
    for (int j = wq; j < cnt; j += 2){
        const int node = (int)(g_gid[off + j] & 15u);
        int mult = 0;
        #pragma unroll
        for (int e = 0; e < EPG; e++){
            int sd = EDGE_SD(A, e);
            mult += ((sd >> 4) == 0 && (sd & 15) == node);
        }
        const float scale = (float)mult * ONRM(B, node);
        const float* row = g_h + (size_t)(off + j)*RK;
        float x[16]; float s = 0.f, ss = 0.f;
        #pragma unroll
        for (int u = 0; u < 16; u++){
            float v = row[lane + 32*u] + b1[lane + 32*u];
            x[u] = v; s += v; ss += v*v;
        }
        s = wredsum(s); ss = wredsum(ss);
        const float mu = s*(1.0f/RK);
        const float rs = rsqrtf(ss*(1.0f/RK) - mu*mu + 1e-5f);
        #pragma unroll
        for (int u = 0; u < 16; u++){
            float y = fmaxf((x[u]-mu)*rs*gam1[lane+32*u] + bet1[lane+32*u], 0.f);
            hs[j][lane + 32*u] = y*scale;
        }
    }
    __syncthreads();

    // stage B: 2 warps split the 512 elements; sum rows, permuted tf32 store
    const float in0 = INRM(B, 0);
    float* dst = g_mc + (size_t)g*RK;
    #pragma unroll
    for (int u = 0; u < 8; u++){
        const int kk = wq*256 + u*32 + lane;
        float val = 0.f;
        for (int j = 0; j < cnt; j++) val += hs[j][kk];
        dst[kperm(kk)] = tf32r(val*in0);
    }
}

// ------------- GEMM1 (mma.sync tf32): g_h = g_m @ W1t, early exit ------------
#define BM 128
#define BN 256
#define BK 32
#define APITCH 40
#define BPITCH 40
#define STAGES 3
#define STG_F (BM*APITCH + BN*BPITCH)
#define SMEM_GEMM (STAGES*STG_F*4)

__global__ __launch_bounds__(256,1) void gemm_tf32_kernel(
    const float* __restrict__ A, const float* __restrict__ Wt,
    float* __restrict__ C, const int* __restrict__ tot)
{
    extern __shared__ float smbuf[];
    const int bn = blockIdx.x, bm = blockIdx.y;
    if (tot && bm*BM >= *tot) return;
    const int tid = threadIdx.x;
    const int lane = tid & 31, warp = tid >> 5;
    const int wm = warp & 1, wn = warp >> 1;
    const int gid = lane >> 2, tig = lane & 3;

    float c[4][8][4];
    #pragma unroll
    for (int mt = 0; mt < 4; mt++)
        #pragma unroll
        for (int nf = 0; nf < 8; nf++)
            #pragma unroll
            for (int q = 0; q < 4; q++) c[mt][nf][q] = 0.f;

    const float* Ag = A  + (size_t)bm*BM*RK;
    const float* Bg = Wt + (size_t)bn*BN*RK;

    auto fill = [&](int t){
        float* As = smbuf + (t % STAGES)*STG_F;
        float* Bs = As + BM*APITCH;
        const int k0 = t*BK;
        #pragma unroll
        for (int i = 0; i < 4; i++){
            int idx = tid + i*256; int r = idx >> 3, cc = idx & 7;
            cp_async16(&As[r*APITCH + cc*4], Ag + (size_t)r*RK + k0 + cc*4);
        }
        #pragma unroll
        for (int i = 0; i < 8; i++){
            int idx = tid + i*256; int r = idx >> 3, cc = idx & 7;
            cp_async16(&Bs[r*BPITCH + cc*4], Bg + (size_t)r*RK + k0 + cc*4);
        }
        cp_commit();
    };

    fill(0); fill(1);

    #pragma unroll 1
    for (int kt = 0; kt < RK/BK; kt++){
        cp_wait<1>();
        __syncthreads();
        if (kt + 2 < RK/BK) fill(kt + 2);
        else cp_commit();

        const float* Ac = smbuf + (kt % STAGES)*STG_F;
        const float* Bc = Ac + BM*APITCH;
        #pragma unroll
        for (int ks = 0; ks < BK/8; ks++){
            const int kp = ks*8 + 2*tig;
            unsigned a[4][4]; unsigned b[8][2];
            #pragma unroll
            for (int mt = 0; mt < 4; mt++){
                int r = wm*64 + mt*16 + gid;
                float2 p0 = *(const float2*)&Ac[ r    *APITCH + kp];
                float2 p1 = *(const float2*)&Ac[(r+8) *APITCH + kp];
                a[mt][0] = __float_as_uint(p0.x);
                a[mt][1] = __float_as_uint(p1.x);
                a[mt][2] = __float_as_uint(p0.y);
                a[mt][3] = __float_as_uint(p1.y);
            }
            #pragma unroll
            for (int nf = 0; nf < 8; nf++){
                int cn = wn*64 + nf*8 + gid;
                float2 pb = *(const float2*)&Bc[cn*BPITCH + kp];
                b[nf][0] = __float_as_uint(pb.x);
                b[nf][1] = __float_as_uint(pb.y);
            }
            #pragma unroll
            for (int mt = 0; mt < 4; mt++)
                #pragma unroll
                for (int nf = 0; nf < 8; nf++)
                    mma_tf32(c[mt][nf], a[mt], b[nf]);
        }
    }
    #pragma unroll
    for (int mt = 0; mt < 4; mt++){
        int r = bm*BM + wm*64 + mt*16 + gid;
        #pragma unroll
        for (int nf = 0; nf < 8; nf++){
            int cn = bn*BN + wn*64 + nf*8 + tig*2;
            *(float2*)&C[(size_t)r*RK + cn]     = make_float2(c[mt][nf][0], c[mt][nf][1]);
            *(float2*)&C[(size_t)(r+8)*RK + cn] = make_float2(c[mt][nf][2], c[mt][nf][3]);
        }
    }
}

// ----- GEMM2 fused with output head: out = relu(LN(mc@W2t + b2))·wout + bout -
#define BM2 64
#define STG2_F (BM2*APITCH + 512*BPITCH)
#define SMEM_G2 (2*STG2_F*4)

__global__ __launch_bounds__(256,1) void gemm2_out_kernel(
    const float* __restrict__ A, const float* __restrict__ Wt,
    const float* __restrict__ b2, const float* __restrict__ gm2,
    const float* __restrict__ bt2, const float* __restrict__ wout,
    const float* __restrict__ bout, float* __restrict__ out)
{
    extern __shared__ float smbuf[];
    const int tid = threadIdx.x, bm = blockIdx.x;
    const int lane = tid & 31, w = tid >> 5;
    const int gid = lane >> 2, tig = lane & 3;

    float c[4][8][4];
    #pragma unroll
    for (int mt = 0; mt < 4; mt++)
        #pragma unroll
        for (int nf = 0; nf < 8; nf++)
            #pragma unroll
            for (int q = 0; q < 4; q++) c[mt][nf][q] = 0.f;

    const float* Ag = A + (size_t)bm*BM2*RK;

    auto fill = [&](int t){
        float* As = smbuf + (t & 1)*STG2_F;
        float* Bs = As + BM2*APITCH;
        const int k0 = t*BK;
        #pragma unroll
        for (int i = 0; i < 2; i++){
            int idx = tid + i*256; int r = idx >> 3, cc = idx & 7;
            cp_async16(&As[r*APITCH + cc*4], Ag + (size_t)r*RK + k0 + cc*4);
        }
        #pragma unroll
        for (int i = 0; i < 16; i++){
            int idx = tid + i*256; int r = idx >> 3, cc = idx & 7;
            cp_async16(&Bs[r*BPITCH + cc*4], Wt + (size_t)r*RK + k0 + cc*4);
        }
        cp_commit();
    };

    fill(0);
    #pragma unroll 1
    for (int kt = 0; kt < RK/BK; kt++){
        if (kt + 1 < RK/BK){ fill(kt + 1); cp_wait<1>(); }
        else               { cp_wait<0>(); }
        __syncthreads();
        const float* Ac = smbuf + (kt & 1)*STG2_F;
        const float* Bc = Ac + BM2*APITCH;
        #pragma unroll
        for (int ks = 0; ks < BK/8; ks++){
            const int kp = ks*8 + 2*tig;
            unsigned a[4][4]; unsigned b[8][2];
            #pragma unroll
            for (int mt = 0; mt < 4; mt++){
                int r = mt*16 + gid;
                float2 p0 = *(const float2*)&Ac[ r    *APITCH + kp];
                float2 p1 = *(const float2*)&Ac[(r+8) *APITCH + kp];
                a[mt][0] = __float_as_uint(p0.x);
                a[mt][1] = __float_as_uint(p1.x);
                a[mt][2] = __float_as_uint(p0.y);
                a[mt][3] = __float_as_uint(p1.y);
            }
            #pragma unroll
            for (int nf = 0; nf < 8; nf++){
                int cn = w*64 + nf*8 + gid;
                float2 pb = *(const float2*)&Bc[cn*BPITCH + kp];
                b[nf][0] = __float_as_uint(pb.x);
                b[nf][1] = __float_as_uint(pb.y);
            }
            #pragma unroll
            for (int mt = 0; mt < 4; mt++)
                #pragma unroll
                for (int nf = 0; nf < 8; nf++)
                    mma_tf32(c[mt][nf], a[mt], b[nf]);
        }
        __syncthreads();
    }

    // fused epilogue: bias -> LN (cross-warp) -> ReLU -> dot(wout)
    float* sS  = smbuf;
    float* sQ  = smbuf + 512;
    float* sMu = smbuf + 1024;
    float* sRs = smbuf + 1088;
    float* sD  = smbuf + 2048;

    float b2v[8][2], g2v[8][2], t2v[8][2], wov[8][2];
    #pragma unroll
    for (int nf = 0; nf < 8; nf++){
        int col = w*64 + nf*8 + tig*2;
        b2v[nf][0] = b2[col];   b2v[nf][1] = b2[col+1];
        g2v[nf][0] = gm2[col];  g2v[nf][1] = gm2[col+1];
        t2v[nf][0] = bt2[col];  t2v[nf][1] = bt2[col+1];
        wov[nf][0] = wout[col]; wov[nf][1] = wout[col+1];
    }
    float ps[4][2], pq[4][2];
    #pragma unroll
    for (int mt = 0; mt < 4; mt++)
        #pragma unroll
        for (int h = 0; h < 2; h++){ ps[mt][h] = 0.f; pq[mt][h] = 0.f; }
    #pragma unroll
    for (int mt = 0; mt < 4; mt++)
        #pragma unroll
        for (int nf = 0; nf < 8; nf++)
            #pragma unroll
            for (int q = 0; q < 4; q++){
                float v = c[mt][nf][q] + b2v[nf][q & 1];
                c[mt][nf][q] = v;
                ps[mt][q >> 1] += v;
                pq[mt][q >> 1] += v*v;
            }
    #pragma unroll
    for (int mt = 0; mt < 4; mt++)
        #pragma unroll
        for (int h = 0; h < 2; h++){
            float s = ps[mt][h], q = pq[mt][h];
            s += __shfl_xor_sync(0xffffffffu, s, 1);
            s += __shfl_xor_sync(0xffffffffu, s, 2);
            q += __shfl_xor_sync(0xffffffffu, q, 1);
            q += __shfl_xor_sync(0xffffffffu, q, 2);
            if (tig == 0){
                int r = mt*16 + 8*h + gid;
                sS[w*64 + r] = s;
                sQ[w*64 + r] = q;
            }
        }
    __syncthreads();
    if (tid < 64){
        float S = 0.f, Q = 0.f;
        #pragma unroll
        for (int ww = 0; ww < 8; ww++){ S += sS[ww*64 + tid]; Q += sQ[ww*64 + tid]; }
        float mu = S*(1.0f/RK);
        sMu[tid] = mu;
        sRs[tid] = rsqrtf(Q*(1.0f/RK) - mu*mu + 1e-5f);
    }
    __syncthreads();
    float pd[4][2];
    #pragma unroll
    for (int mt = 0; mt < 4; mt++)
        #pragma unroll
        for (int h = 0; h < 2; h++){
            int r = mt*16 + 8*h + gid;
            float mu = sMu[r], rs = sRs[r];
            float acc = 0.f;
            #pragma unroll
            for (int nf = 0; nf < 8; nf++)
                #pragma unroll
                for (int qq = 0; qq < 2; qq++){
                    float y = fmaxf((c[mt][nf][2*h+qq] - mu)*rs*g2v[nf][qq] + t2v[nf][qq], 0.f);
                    acc = fmaf(y, wov[nf][qq], acc);
                }
            pd[mt][h] = acc;
        }
    #pragma unroll
    for (int mt = 0; mt < 4; mt++)
        #pragma unroll
        for (int h = 0; h < 2; h++){
            float s = pd[mt][h];
            s += __shfl_xor_sync(0xffffffffu, s, 1);
            s += __shfl_xor_sync(0xffffffffu, s, 2);
            if (tig == 0) sD[w*64 + mt*16 + 8*h + gid] = s;
        }
    __syncthreads();
    if (tid < 64){
        float dot = 0.f;
        #pragma unroll
        for (int ww = 0; ww < 8; ww++) dot += sD[ww*64 + tid];
        out[bm*BM2 + tid] = dot + bout[0];
    }
}

// ---------------- launcher ---------------------------------------------------
extern "C" void kernel_launch(void* const* d_in, const int* in_sizes, int n_in,
                              void* d_out, int out_size){
    (void)in_sizes; (void)n_in; (void)out_size;
    const void*  feat = d_in[0];
    const void*  src  = d_in[1];
    const void*  dst  = d_in[2];
    const float* emb  = (const float*)d_in[3];
    const float* Ws   = (const float*)d_in[4];
    const float* bs   = (const float*)d_in[5];
    const float* gam  = (const float*)d_in[6];
    const float* bet  = (const float*)d_in[7];
    const float* wout = (const float*)d_in[8];
    const float* bout = (const float*)d_in[9];
    float* out = (float*)d_out;

    cudaFuncSetAttribute(gemm_tf32_kernel,
                         cudaFuncAttributeMaxDynamicSharedMemorySize, SMEM_GEMM);
    cudaFuncSetAttribute(gemm2_out_kernel,
                         cudaFuncAttributeMaxDynamicSharedMemorySize, SMEM_G2);
    cudaFuncSetAttribute(fuse1_kernel,
                         cudaFuncAttributeMaxDynamicSharedMemorySize, F1_SMEM);
    cudaFuncSetAttribute(fuseD_kernel,
                         cudaFuncAttributeMaxDynamicSharedMemorySize, F1_SMEM);

    float* gm;  cudaGetSymbolAddress((void**)&gm,  g_m);
    float* gh;  cudaGetSymbolAddress((void**)&gh,  g_h);
    float* gmc; cudaGetSymbolAddress((void**)&gmc, g_mc);
    float* gwt; cudaGetSymbolAddress((void**)&gwt, g_Wt);
    int*   gtot; cudaGetSymbolAddress((void**)&gtot, g_total);

    prep_kernel<<<525, 256>>>(Ws, emb, (const int*)src, (const int*)feat);
    meta_kernel<<<NB/256, 256>>>(feat, src, dst);
    scan_kernel<<<1, 1024>>>();

    fuse1_kernel<<<NB/F1_G, 256, F1_SMEM>>>(bs, gam, bet);
    dim3 gg(RK/BN, NN/BM);                 // worst case; early exit on g_total
    gemm_tf32_kernel<<<gg, 256, SMEM_GEMM>>>(gm, gwt + RK*RK, gh, gtot);
    fuseD_kernel<<<NB/F1_G, 256, F1_SMEM>>>(bs + RK, gam + RK, bet + RK);
    gemm2_out_kernel<<<NB/BM2, 256, SMEM_G2>>>(gmc, gwt + 2*(size_t)RK*RK,
        bs + 2*RK, gam + 2*RK, bet + 2*RK, wout, bout, out);
}